// round 8
// baseline (speedup 1.0000x reference)
#include <cuda_runtime.h>
#include <math.h>

#define GRID_N   16
#define IN_DIM   64
#define OUT_DIM  64
#define BATCH    1024
#define NCOEF    19

#define BT 16                 // batch tile
#define OB 4                  // o-columns per block
#define THREADS 256

// float4 SMEM layout: cst [i][m][oo] (1216 f4), xs [bb][i4] pitch 17 (272 f4),
// S4 [oo][bb][i4^swz] (1024 f4).  Total 2512 f4 = 40192 B -> 5 CTAs/SM.
#define CST_Q4   1216
#define XS_Q4    (BT * 17)                 // 272
#define S4_Q4    (OB * BT * 16)            // 1024
#define SMEM_BYTES ((CST_Q4 + XS_Q4 + S4_Q4) * 16)   // 40192

__global__ __launch_bounds__(THREADS, 5)
void kan_kernel(const float* __restrict__ x,
                const float* __restrict__ coef,
                const float* __restrict__ grid,
                float* __restrict__ out) {
    extern __shared__ float4 sm4[];
    float4* cst4 = sm4;                    // coef transposed [i][m][oo]
    float4* xs4  = sm4 + CST_Q4;           // x tile [bb][i4], pitch 17
    float4* S4   = sm4 + CST_Q4 + XS_Q4;   // results [oo][bb][i4 swizzled]
    float*  csts = (float*)cst4;

    const int tid = threadIdx.x;
    const int b0  = (blockIdx.x & 63) * BT;
    const int o0  = (blockIdx.x >> 6) * OB;

    // ---- Stage coef tile: coalesced LDG.128, scatter-STS into [i][m][oo].
    {
        const float4* src = (const float4*)coef + (size_t)o0 * (IN_DIM * NCOEF / 4);
        #pragma unroll
        for (int p = tid; p < CST_Q4; p += THREADS) {
            float4 v = __ldg(src + p);
            int e = p * 4;
            #pragma unroll
            for (int c = 0; c < 4; c++) {
                int ec = e + c;
                int oo  = ec / (IN_DIM * NCOEF);
                int rem = ec - oo * (IN_DIM * NCOEF);
                int i   = rem / NCOEF;
                int m   = rem - i * NCOEF;
                float val = (c == 0) ? v.x : (c == 1) ? v.y : (c == 2) ? v.z : v.w;
                csts[(i * NCOEF + m) * 4 + oo] = val;
            }
        }
        // x tile: one float4 per thread, coalesced.
        int row = tid >> 4, col = tid & 15;
        xs4[row * 17 + col] = __ldg((const float4*)x + (size_t)(b0 + row) * 16 + col);
    }
    const float g3    = __ldg(grid + 3);
    const float inv_h = 1.0f / (__ldg(grid + 4) - g3);
    const float k6    = 1.0f / 6.0f;
    __syncthreads();

    // ---- Compute: thread = (bb, 4 consecutive i); 16 outputs (4 i x 4 o).
    {
        const int lane = tid & 31;
        const int w    = tid >> 5;
        const int bb   = lane & 15;
        const int ih   = lane >> 4;
        const int i4   = w * 2 + ih;        // float4-column over i
        const int ibase = i4 * 4;

        float4 xv4 = xs4[bb * 17 + i4];     // 4 x-values (LDS.128)
        float4 racc[OB];                    // [oo], components = j (i within quad)

        #pragma unroll
        for (int j = 0; j < 4; j++) {
            const float xv = (j == 0) ? xv4.x : (j == 1) ? xv4.y : (j == 2) ? xv4.z : xv4.w;
            float t = (xv - g3) * inv_h;
            int i0 = (int)floorf(t);
            i0 = min(GRID_N - 1, max(0, i0));
            const float u  = t - (float)i0;
            const float om = 1.0f - u;
            const float u2 = u * u;
            const float w0 = om * om * om * k6;
            const float w3 = u2 * u * k6;
            const float w1 = fmaf(u2, fmaf(0.5f, u, -1.0f), 2.0f / 3.0f);
            const float w2 = 1.0f - w0 - w1 - w3;

            // One LDS.128 per tap serves all 4 o-outputs.
            const float4* c = cst4 + (ibase + j) * NCOEF + i0;
            float4 c0 = c[0], c1 = c[1], c2 = c[2], c3 = c[3];
            float r0 = fmaf(w3, c3.x, fmaf(w2, c2.x, fmaf(w1, c1.x, w0 * c0.x)));
            float r1 = fmaf(w3, c3.y, fmaf(w2, c2.y, fmaf(w1, c1.y, w0 * c0.y)));
            float r2 = fmaf(w3, c3.z, fmaf(w2, c2.z, fmaf(w1, c1.z, w0 * c0.z)));
            float r3 = fmaf(w3, c3.w, fmaf(w2, c2.w, fmaf(w1, c1.w, w0 * c0.w)));
            ((float*)&racc[0])[j] = r0;     // in-register [j][oo] -> [oo][j]
            ((float*)&racc[1])[j] = r1;
            ((float*)&racc[2])[j] = r2;
            ((float*)&racc[3])[j] = r3;
        }

        const int sw = bb & 7;
        #pragma unroll
        for (int oo = 0; oo < OB; oo++)     // XOR-swizzled STS.128, 4-phase
            S4[oo * (BT * 16) + bb * 16 + (i4 ^ sw)] = racc[oo];
    }
    __syncthreads();

    // ---- Store: 1024 float4, 4/thread, coalesced STG.128 (256B rows).
    #pragma unroll
    for (int r = 0; r < 4; r++) {
        int idx = tid + r * THREADS;
        int i4s = idx & 15;
        int o   = (idx >> 4) & 3;
        int bbs = idx >> 6;
        float4 v = S4[o * (BT * 16) + bbs * 16 + (i4s ^ (bbs & 7))];
        reinterpret_cast<float4*>(out)[
            ((size_t)(b0 + bbs) * OUT_DIM + (o0 + o)) * (IN_DIM / 4) + i4s] = v;
    }
}

extern "C" void kernel_launch(void* const* d_in, const int* in_sizes, int n_in,
                              void* d_out, int out_size) {
    const float* x    = (const float*)d_in[0];
    const float* coef = (const float*)d_in[1];
    const float* grid = (const float*)d_in[2];
    float* out        = (float*)d_out;

    cudaFuncSetAttribute(kan_kernel, cudaFuncAttributeMaxDynamicSharedMemorySize,
                         SMEM_BYTES);
    kan_kernel<<<(BATCH / BT) * (OUT_DIM / OB), THREADS, SMEM_BYTES>>>(x, coef, grid, out);
}

// round 10
// speedup vs baseline: 1.7881x; 1.7881x over previous
#include <cuda_runtime.h>
#include <math.h>

#define GRID_N   16
#define IN_DIM   64
#define OUT_DIM  64
#define BATCH    1024
#define NCOEF    19

#define BT 32                 // batch tile (warp lanes = b)
#define OB 4                  // o-columns per block
#define THREADS 256

#define CS_F     (OB * IN_DIM * NCOEF)     // 4864 floats coef tile [oo][i][19]
#define S4_Q4    (OB * BT * 16)            // 2048 float4 result buffer
// region2 = union(xs tile [32][17] f4 = 544 f4, S4 2048 f4) -> 2048 f4
#define SMEM_BYTES ((CS_F + S4_Q4 * 4) * 4)   // 52224 B -> 4 CTAs/SM

__global__ __launch_bounds__(THREADS, 4)
void kan_kernel(const float* __restrict__ x,
                const float* __restrict__ coef,
                const float* __restrict__ grid,
                float* __restrict__ out) {
    extern __shared__ float sm[];
    float*  cs  = sm;                          // coef [oo][i][19]
    float4* xs4 = (float4*)(sm + CS_F);        // phase A: x tile [b][i4] pitch 17
    float4* S4  = (float4*)(sm + CS_F);        // phase B: results (same region)

    const int tid  = threadIdx.x;
    const int b0   = (blockIdx.x & 31) * BT;   // 32 batch tiles
    const int o0   = (blockIdx.x >> 5) * OB;   // 16 o-chunks
    const int lane = tid & 31;                 // -> b
    const int warp = tid >> 5;                 // -> i-group of 8

    // ---- Stage coef tile + x tile (both coalesced LDG.128).
    {
        // NOTE: per-o row stride is IN_DIM*NCOEF (R9 bug: used CS_F = 4x stride).
        const float4* src = (const float4*)(coef + (size_t)o0 * IN_DIM * NCOEF);
        #pragma unroll
        for (int t = tid; t < CS_F / 4; t += THREADS)
            ((float4*)cs)[t] = src[t];
        #pragma unroll
        for (int k = 0; k < 2; k++) {          // 512 f4 of x, 2 per thread
            int idx = tid + k * THREADS;
            int row = idx >> 4, col = idx & 15;
            xs4[row * 17 + col] = ((const float4*)x)[(size_t)(b0 + row) * 16 + col];
        }
    }
    const float g3    = grid[3];
    const float inv_h = 1.0f / (grid[4] - g3);
    const float k6    = 1.0f / 6.0f;
    __syncthreads();

    // ---- Phase A: consume xs into registers; compute all weights up front.
    float w0[2][4], w1[2][4], w2[2][4], w3[2][4];
    int   base[2][4];
    #pragma unroll
    for (int g = 0; g < 2; g++) {
        float4 xq = xs4[lane * 17 + warp * 2 + g];   // LDS.128, pitch-17 conflict-free
        #pragma unroll
        for (int j = 0; j < 4; j++) {
            const float xv = (j == 0) ? xq.x : (j == 1) ? xq.y : (j == 2) ? xq.z : xq.w;
            float t = (xv - g3) * inv_h;
            int i0 = (int)floorf(t);
            i0 = min(GRID_N - 1, max(0, i0));
            const float u  = t - (float)i0;
            const float om = 1.0f - u;
            const float u2 = u * u;
            w0[g][j] = om * om * om * k6;
            w3[g][j] = u2 * u * k6;
            w1[g][j] = fmaf(u2, fmaf(0.5f, u, -1.0f), 2.0f / 3.0f);
            w2[g][j] = 1.0f - w0[g][j] - w1[g][j] - w3[g][j];
            base[g][j] = (warp * 8 + g * 4 + j) * NCOEF + i0;
        }
    }
    __syncthreads();   // xs fully consumed -> region becomes S4

    // ---- Phase B: SMEM gathers (R5 geometry: lanes=b, 19-word window, conflict-free).
    #pragma unroll
    for (int g = 0; g < 2; g++) {
        const int i4 = warp * 2 + g;
        #pragma unroll
        for (int oo = 0; oo < OB; oo++) {
            const float* c = cs + oo * (IN_DIM * NCOEF);
            float4 r;
            r.x = fmaf(w3[g][0], c[base[g][0] + 3], fmaf(w2[g][0], c[base[g][0] + 2],
                  fmaf(w1[g][0], c[base[g][0] + 1], w0[g][0] * c[base[g][0]])));
            r.y = fmaf(w3[g][1], c[base[g][1] + 3], fmaf(w2[g][1], c[base[g][1] + 2],
                  fmaf(w1[g][1], c[base[g][1] + 1], w0[g][1] * c[base[g][1]])));
            r.z = fmaf(w3[g][2], c[base[g][2] + 3], fmaf(w2[g][2], c[base[g][2] + 2],
                  fmaf(w1[g][2], c[base[g][2] + 1], w0[g][2] * c[base[g][2]])));
            r.w = fmaf(w3[g][3], c[base[g][3] + 3], fmaf(w2[g][3], c[base[g][3] + 2],
                  fmaf(w1[g][3], c[base[g][3] + 1], w0[g][3] * c[base[g][3]])));
            // XOR swizzle: write col = i4 ^ (lane&15); read inverts it -> bijective.
            S4[(oo * BT + lane) * 16 + (i4 ^ (lane & 15))] = r;
        }
    }
    __syncthreads();

    // ---- Store: 2048 float4, 8/thread; reads = contiguous 256B rows, STG coalesced.
    #pragma unroll
    for (int k = 0; k < 8; k++) {
        int t   = tid + k * THREADS;
        int i4s = t & 15;
        int oo  = (t >> 4) & 3;
        int bb  = t >> 6;
        float4 v = S4[(oo * BT + bb) * 16 + (i4s ^ (bb & 15))];
        reinterpret_cast<float4*>(out)[
            ((size_t)(b0 + bb) * OUT_DIM + (o0 + oo)) * (IN_DIM / 4) + i4s] = v;
    }
}

extern "C" void kernel_launch(void* const* d_in, const int* in_sizes, int n_in,
                              void* d_out, int out_size) {
    const float* x    = (const float*)d_in[0];
    const float* coef = (const float*)d_in[1];
    const float* grid = (const float*)d_in[2];
    float* out        = (float*)d_out;

    cudaFuncSetAttribute(kan_kernel, cudaFuncAttributeMaxDynamicSharedMemorySize,
                         SMEM_BYTES);
    kan_kernel<<<(BATCH / BT) * (OUT_DIM / OB), THREADS, SMEM_BYTES>>>(x, coef, grid, out);
}